// round 13
// baseline (speedup 1.0000x reference)
#include <cuda_runtime.h>
#include <cuda_fp16.h>
#include <math.h>

#define S   160
#define SQ  40          // S/4 quads per row (quad = 4 elems)
#define R   9           // 9x 3-erosion == one 19-window (clamped)
#define TY  32
#define TZ  32
#define NT  320         // 40 quads * 8 groups
#define NBLOCKS_B ((S / TZ) * S * 4)   // 3200
#define NQUADS (4 * S * S * SQ)        // total fp16-quad (uint2) count

// Scratch: eroded-xy field as packed fp16 quads (uint2 => 8B alignment
// guaranteed by type). min is monotonic => rounding target to fp16 before
// the min cascade equals rounding the true eroded field once at the end.
__device__ uint2        g_exy[NQUADS];
__device__ double       g_acc[3];
__device__ unsigned int g_done;   // zero-init; last block resets it each replay

__device__ __forceinline__ int clampi(int v, int lo, int hi) {
    return v < lo ? lo : (v > hi ? hi : v);
}

// ---- fp16 helpers -------------------------------------------------------
__device__ __forceinline__ unsigned h2_to_u(__half2 h) {
    return ((unsigned)__half_as_ushort(__high2half(h)) << 16) |
            (unsigned)__half_as_ushort(__low2half(h));
}
__device__ __forceinline__ __half2 u_to_h2(unsigned u) {
    return __halves2half2(__ushort_as_half((unsigned short)(u & 0xFFFFu)),
                          __ushort_as_half((unsigned short)(u >> 16)));
}
__device__ __forceinline__ unsigned umin2(unsigned a, unsigned b) {
    return h2_to_u(__hmin2(u_to_h2(a), u_to_h2(b)));
}
struct H4 { __half2 a, b; };
__device__ __forceinline__ H4 h4min(H4 x, H4 y) {
    H4 r; r.a = __hmin2(x.a, y.a); r.b = __hmin2(x.b, y.b); return r;
}
__device__ __forceinline__ H4 h4_from_u2(uint2 u) {
    H4 r; r.a = u_to_h2(u.x); r.b = u_to_h2(u.y); return r;
}
__device__ __forceinline__ uint2 u2_from_h4(H4 h) {
    uint2 u; u.x = h2_to_u(h.a); u.y = h2_to_u(h.b); return u;
}

// ---------------------------------------------------------------------------
// Pass A: fused 19-min over y then x, entirely in fp16. (Unchanged from R10.)
// ---------------------------------------------------------------------------
__global__ void __launch_bounds__(NT) minxy_kernel(const float4* __restrict__ in4,
                                                   uint2* __restrict__ outh) {
    extern __shared__ uint2 smu[];
    uint2* A = smu;                  // 50*40
    uint2* C = smu + 50 * SQ;        // 32*40

    const int tid = threadIdx.x;
    const int q   = tid % SQ;
    const int g   = tid / SQ;        // 0..7
    const int y0  = blockIdx.x * TY;
    const int z   = blockIdx.y;
    const int b   = blockIdx.z;
    const long long base4 = (long long)(b * S + z) * S * SQ;

    if (blockIdx.x == 0 && blockIdx.y == 0 && blockIdx.z == 0 && tid < 3)
        g_acc[tid] = 0.0;

    // Load 50 y-rows (clamped halo), convert fp32->fp16 at load.
    for (int i = tid; i < 50 * SQ; i += NT) {
        const int r = i / SQ, qq = i % SQ;
        const int y = clampi(y0 - R + r, 0, S - 1);
        const float4 f = in4[base4 + y * SQ + qq];
        uint2 u;
        u.x = h2_to_u(__floats2half2_rn(f.x, f.y));
        u.y = h2_to_u(__floats2half2_rn(f.z, f.w));
        A[i] = u;
    }
    __syncthreads();

    // y-min: group of 4 outputs shares a 16-row tree-min core (fp16 SIMD).
    {
        const int o = 4 * g;
        const uint2* col = A + q;
        H4 p0 = h4min(h4_from_u2(col[(o + 3) * SQ]),  h4_from_u2(col[(o + 4) * SQ]));
        H4 p1 = h4min(h4_from_u2(col[(o + 5) * SQ]),  h4_from_u2(col[(o + 6) * SQ]));
        H4 p2 = h4min(h4_from_u2(col[(o + 7) * SQ]),  h4_from_u2(col[(o + 8) * SQ]));
        H4 p3 = h4min(h4_from_u2(col[(o + 9) * SQ]),  h4_from_u2(col[(o + 10) * SQ]));
        H4 p4 = h4min(h4_from_u2(col[(o + 11) * SQ]), h4_from_u2(col[(o + 12) * SQ]));
        H4 p5 = h4min(h4_from_u2(col[(o + 13) * SQ]), h4_from_u2(col[(o + 14) * SQ]));
        H4 p6 = h4min(h4_from_u2(col[(o + 15) * SQ]), h4_from_u2(col[(o + 16) * SQ]));
        H4 p7 = h4min(h4_from_u2(col[(o + 17) * SQ]), h4_from_u2(col[(o + 18) * SQ]));
        H4 core = h4min(h4min(h4min(p0, p1), h4min(p2, p3)),
                        h4min(h4min(p4, p5), h4min(p6, p7)));
        H4 a0 = h4_from_u2(col[(o + 0) * SQ]),  a1 = h4_from_u2(col[(o + 1) * SQ]);
        H4 a2 = h4_from_u2(col[(o + 2) * SQ]);
        H4 b0 = h4_from_u2(col[(o + 19) * SQ]), b1 = h4_from_u2(col[(o + 20) * SQ]);
        H4 b2 = h4_from_u2(col[(o + 21) * SQ]);
        C[(o + 0) * SQ + q] = u2_from_h4(h4min(h4min(a0, a1),   h4min(a2, core)));
        C[(o + 1) * SQ + q] = u2_from_h4(h4min(h4min(a1, a2),   h4min(core, b0)));
        C[(o + 2) * SQ + q] = u2_from_h4(h4min(h4min(a2, core), h4min(b0, b1)));
        C[(o + 3) * SQ + q] = u2_from_h4(h4min(h4min(core, b0), h4min(b1, b2)));
    }
    __syncthreads();

    // x-min: SIMD-paired windows via PRMT slices (see R10 comments).
#pragma unroll
    for (int k = 0; k < 4; ++k) {
        const int i = tid + NT * k;          // 0..1279 exactly
        const int row = i / SQ, qq = i % SQ;
        unsigned h[14];
#pragma unroll
        for (int dq = -3; dq <= 3; ++dq) {
            const uint2 c = C[row * SQ + clampi(qq + dq, 0, SQ - 1)];
            h[2 * (dq + 3)]     = c.x;
            h[2 * (dq + 3) + 1] = c.y;
        }
        unsigned s[21];
#pragma unroll
        for (int j = 0; j < 21; ++j) {
            const int d = j - 9;
            if ((d & 1) == 0) {
                s[j] = h[(d + 12) >> 1];
            } else {
                s[j] = __byte_perm(h[(d + 11) >> 1], h[(d + 13) >> 1], 0x5432);
            }
        }
        unsigned c0 = umin2(s[2],  s[3]),  c1 = umin2(s[4],  s[5]);
        unsigned c2 = umin2(s[6],  s[7]),  c3 = umin2(s[8],  s[9]);
        unsigned c4 = umin2(s[10], s[11]), c5 = umin2(s[12], s[13]);
        unsigned c6 = umin2(s[14], s[15]), c7 = umin2(s[16], s[17]);
        unsigned d0 = umin2(c0, c1), d1 = umin2(c2, c3);
        unsigned d2 = umin2(c4, c5), d3 = umin2(c6, c7);
        unsigned core = umin2(umin2(umin2(d0, d1), umin2(d2, d3)), s[18]);
        uint2 r;
        r.x = umin2(umin2(s[0],  s[1]),  core);
        r.y = umin2(umin2(s[19], s[20]), core);
        outh[base4 + (long long)(y0 + row) * SQ + qq] = r;
    }
}

// ---------------------------------------------------------------------------
// Pass B: 19-min over z (fp16 tree) fused with the weighted-dice reduction.
// pred/targ are prefetched into registers BEFORE the smem fill so their
// DRAM latency overlaps the exy staging + barrier + min tree.
// ---------------------------------------------------------------------------
__global__ void __launch_bounds__(NT) minz_reduce_kernel(const uint2* __restrict__ exyh,
                                                         const float4* __restrict__ pred4,
                                                         const float4* __restrict__ targ4,
                                                         float* __restrict__ out) {
    __shared__ uint2 s2[50 * SQ];            // 16000 B
    __shared__ float wsum[NT / 32][3];

    const int tid = threadIdx.x;
    const int q   = tid % SQ;
    const int g   = tid / SQ;                // 0..7
    const int o   = 4 * g;
    const int z0  = blockIdx.x * TZ;
    const int y   = blockIdx.y;
    const int b   = blockIdx.z;
    const long long bbase4 = (long long)b * S * S * SQ;

    // ---- prefetch pred/targ (addresses independent of smem phase) ----
    float4 pf[4], tf[4];
#pragma unroll
    for (int j = 0; j < 4; ++j) {
        const long long idx4 = bbase4 + (long long)(z0 + o + j) * S * SQ + y * SQ + q;
        pf[j] = pred4[idx4];
        tf[j] = targ4[idx4];
    }

    // ---- stage exy z-rows in smem (overlaps with the prefetch) ----
    for (int i = tid; i < 50 * SQ; i += NT) {
        const int r = i / SQ, qq = i % SQ;
        const int z = clampi(z0 - R + r, 0, S - 1);
        s2[i] = exyh[bbase4 + (long long)z * S * SQ + y * SQ + qq];
    }
    __syncthreads();

    const uint2* col = s2 + q;
    H4 p0 = h4min(h4_from_u2(col[(o + 3) * SQ]),  h4_from_u2(col[(o + 4) * SQ]));
    H4 p1 = h4min(h4_from_u2(col[(o + 5) * SQ]),  h4_from_u2(col[(o + 6) * SQ]));
    H4 p2 = h4min(h4_from_u2(col[(o + 7) * SQ]),  h4_from_u2(col[(o + 8) * SQ]));
    H4 p3 = h4min(h4_from_u2(col[(o + 9) * SQ]),  h4_from_u2(col[(o + 10) * SQ]));
    H4 p4 = h4min(h4_from_u2(col[(o + 11) * SQ]), h4_from_u2(col[(o + 12) * SQ]));
    H4 p5 = h4min(h4_from_u2(col[(o + 13) * SQ]), h4_from_u2(col[(o + 14) * SQ]));
    H4 p6 = h4min(h4_from_u2(col[(o + 15) * SQ]), h4_from_u2(col[(o + 16) * SQ]));
    H4 p7 = h4min(h4_from_u2(col[(o + 17) * SQ]), h4_from_u2(col[(o + 18) * SQ]));
    H4 core = h4min(h4min(h4min(p0, p1), h4min(p2, p3)),
                    h4min(h4min(p4, p5), h4min(p6, p7)));
    H4 a0 = h4_from_u2(col[(o + 0) * SQ]),  a1 = h4_from_u2(col[(o + 1) * SQ]);
    H4 a2 = h4_from_u2(col[(o + 2) * SQ]);
    H4 b0 = h4_from_u2(col[(o + 19) * SQ]), b1 = h4_from_u2(col[(o + 20) * SQ]);
    H4 b2 = h4_from_u2(col[(o + 21) * SQ]);
    H4 e[4];
    e[0] = h4min(h4min(a0, a1),   h4min(a2, core));
    e[1] = h4min(h4min(a1, a2),   h4min(core, b0));
    e[2] = h4min(h4min(a2, core), h4min(b0, b1));
    e[3] = h4min(h4min(core, b0), h4min(b1, b2));

    float aI = 0.f, aP = 0.f, aT = 0.f;
#pragma unroll
    for (int j = 0; j < 4; ++j) {
        const float4 p = pf[j];
        const float4 t = tf[j];
        const float2 elo = __half22float2(e[j].a);
        const float2 ehi = __half22float2(e[j].b);
        float w, wp;
        w = fmaf(t.x - elo.x, 5.0f, 1.0f); wp = w * p.x;
        aI = fmaf(wp, t.x, aI); aP += wp; aT = fmaf(w, t.x, aT);
        w = fmaf(t.y - elo.y, 5.0f, 1.0f); wp = w * p.y;
        aI = fmaf(wp, t.y, aI); aP += wp; aT = fmaf(w, t.y, aT);
        w = fmaf(t.z - ehi.x, 5.0f, 1.0f); wp = w * p.z;
        aI = fmaf(wp, t.z, aI); aP += wp; aT = fmaf(w, t.z, aT);
        w = fmaf(t.w - ehi.y, 5.0f, 1.0f); wp = w * p.w;
        aI = fmaf(wp, t.w, aI); aP += wp; aT = fmaf(w, t.w, aT);
    }

#pragma unroll
    for (int off = 16; off > 0; off >>= 1) {
        aI += __shfl_down_sync(0xFFFFFFFFu, aI, off);
        aP += __shfl_down_sync(0xFFFFFFFFu, aP, off);
        aT += __shfl_down_sync(0xFFFFFFFFu, aT, off);
    }
    const int wid = tid >> 5, lane = tid & 31;
    if (lane == 0) { wsum[wid][0] = aI; wsum[wid][1] = aP; wsum[wid][2] = aT; }
    __syncthreads();

    if (tid == 0) {
        double I = 0.0, P = 0.0, T = 0.0;
#pragma unroll
        for (int w = 0; w < NT / 32; ++w) {
            I += (double)wsum[w][0];
            P += (double)wsum[w][1];
            T += (double)wsum[w][2];
        }
        atomicAdd(&g_acc[0], I);
        atomicAdd(&g_acc[1], P);
        atomicAdd(&g_acc[2], T);
        __threadfence();
        const unsigned int n = atomicAdd(&g_done, 1u);
        if (n == NBLOCKS_B - 1) {
            g_done = 0;   // reset for next graph replay (only this block alive)
            const double fI = atomicAdd(&g_acc[0], 0.0);
            const double fP = atomicAdd(&g_acc[1], 0.0);
            const double fT = atomicAdd(&g_acc[2], 0.0);
            const double dice = (2.0 * fI + 1e-5) / (fP + fT + 1e-5);
            out[0] = (float)(1.0 - dice);
        }
    }
}

// ---------------------------------------------------------------------------
extern "C" void kernel_launch(void* const* d_in, const int* in_sizes, int n_in,
                              void* d_out, int out_size) {
    const float4* pred = (const float4*)d_in[0];
    const float4* targ = (const float4*)d_in[1];
    float* out = (float*)d_out;
    (void)in_sizes; (void)n_in; (void)out_size;

    uint2* exy; cudaGetSymbolAddress((void**)&exy, g_exy);

    const int smemA = (50 + TY) * SQ * (int)sizeof(uint2);   // 26240 B
    cudaFuncSetAttribute(minxy_kernel, cudaFuncAttributeMaxDynamicSharedMemorySize, smemA);

    dim3 gridA(S / TY, S, 4);    // (5, 160, 4)
    minxy_kernel<<<gridA, NT, smemA>>>(targ, exy);

    dim3 gridB(S / TZ, S, 4);    // (5, 160, 4)
    minz_reduce_kernel<<<gridB, NT>>>(exy, pred, targ, out);
}

// round 14
// speedup vs baseline: 1.1763x; 1.1763x over previous
#include <cuda_runtime.h>
#include <cuda_fp16.h>
#include <math.h>

#define S   160
#define SQ  40          // S/4 quads per row (quad = 4 fp16 elems, uint2)
#define SQ2 20          // uint4 (2 quads) per row
#define R   9           // 9x 3-erosion == one 19-window (clamped)
#define TY  32
#define TZ  32
#define NT  320         // 40 quads * 8 groups
#define NBLOCKS_B ((S / TZ) * S * 4)   // 3200
#define NQUADS (4 * S * S * SQ)        // total fp16-quad count

// Scratch: eroded-xy field as packed fp16, declared as uint4 so the buffer is
// 16B-aligned by type (pass B fills smem with LDG.128/STS.128; pass A writes
// through an 8B-aligned uint2 view). min is monotonic => rounding target to
// fp16 before the min cascade equals rounding the true eroded field once.
__device__ uint4        g_exy[NQUADS / 2];
__device__ double       g_acc[3];
__device__ unsigned int g_done;   // zero-init; last block resets it each replay

__device__ __forceinline__ int clampi(int v, int lo, int hi) {
    return v < lo ? lo : (v > hi ? hi : v);
}

// ---- fp16 helpers -------------------------------------------------------
__device__ __forceinline__ unsigned h2_to_u(__half2 h) {
    return ((unsigned)__half_as_ushort(__high2half(h)) << 16) |
            (unsigned)__half_as_ushort(__low2half(h));
}
__device__ __forceinline__ __half2 u_to_h2(unsigned u) {
    return __halves2half2(__ushort_as_half((unsigned short)(u & 0xFFFFu)),
                          __ushort_as_half((unsigned short)(u >> 16)));
}
__device__ __forceinline__ unsigned umin2(unsigned a, unsigned b) {
    return h2_to_u(__hmin2(u_to_h2(a), u_to_h2(b)));
}
struct H4 { __half2 a, b; };
__device__ __forceinline__ H4 h4min(H4 x, H4 y) {
    H4 r; r.a = __hmin2(x.a, y.a); r.b = __hmin2(x.b, y.b); return r;
}
__device__ __forceinline__ H4 h4_from_u2(uint2 u) {
    H4 r; r.a = u_to_h2(u.x); r.b = u_to_h2(u.y); return r;
}
__device__ __forceinline__ uint2 u2_from_h4(H4 h) {
    uint2 u; u.x = h2_to_u(h.a); u.y = h2_to_u(h.b); return u;
}

// ---------------------------------------------------------------------------
// Pass A: fused 19-min over y then x, entirely in fp16. (Unchanged from R10.)
// ---------------------------------------------------------------------------
__global__ void __launch_bounds__(NT) minxy_kernel(const float4* __restrict__ in4,
                                                   uint2* __restrict__ outh) {
    extern __shared__ uint2 smu[];
    uint2* A = smu;                  // 50*40
    uint2* C = smu + 50 * SQ;        // 32*40

    const int tid = threadIdx.x;
    const int q   = tid % SQ;
    const int g   = tid / SQ;        // 0..7
    const int y0  = blockIdx.x * TY;
    const int z   = blockIdx.y;
    const int b   = blockIdx.z;
    const long long base4 = (long long)(b * S + z) * S * SQ;

    if (blockIdx.x == 0 && blockIdx.y == 0 && blockIdx.z == 0 && tid < 3)
        g_acc[tid] = 0.0;

    // Load 50 y-rows (clamped halo), convert fp32->fp16 at load.
    for (int i = tid; i < 50 * SQ; i += NT) {
        const int r = i / SQ, qq = i % SQ;
        const int y = clampi(y0 - R + r, 0, S - 1);
        const float4 f = in4[base4 + y * SQ + qq];
        uint2 u;
        u.x = h2_to_u(__floats2half2_rn(f.x, f.y));
        u.y = h2_to_u(__floats2half2_rn(f.z, f.w));
        A[i] = u;
    }
    __syncthreads();

    // y-min: group of 4 outputs shares a 16-row tree-min core (fp16 SIMD).
    {
        const int o = 4 * g;
        const uint2* col = A + q;
        H4 p0 = h4min(h4_from_u2(col[(o + 3) * SQ]),  h4_from_u2(col[(o + 4) * SQ]));
        H4 p1 = h4min(h4_from_u2(col[(o + 5) * SQ]),  h4_from_u2(col[(o + 6) * SQ]));
        H4 p2 = h4min(h4_from_u2(col[(o + 7) * SQ]),  h4_from_u2(col[(o + 8) * SQ]));
        H4 p3 = h4min(h4_from_u2(col[(o + 9) * SQ]),  h4_from_u2(col[(o + 10) * SQ]));
        H4 p4 = h4min(h4_from_u2(col[(o + 11) * SQ]), h4_from_u2(col[(o + 12) * SQ]));
        H4 p5 = h4min(h4_from_u2(col[(o + 13) * SQ]), h4_from_u2(col[(o + 14) * SQ]));
        H4 p6 = h4min(h4_from_u2(col[(o + 15) * SQ]), h4_from_u2(col[(o + 16) * SQ]));
        H4 p7 = h4min(h4_from_u2(col[(o + 17) * SQ]), h4_from_u2(col[(o + 18) * SQ]));
        H4 core = h4min(h4min(h4min(p0, p1), h4min(p2, p3)),
                        h4min(h4min(p4, p5), h4min(p6, p7)));
        H4 a0 = h4_from_u2(col[(o + 0) * SQ]),  a1 = h4_from_u2(col[(o + 1) * SQ]);
        H4 a2 = h4_from_u2(col[(o + 2) * SQ]);
        H4 b0 = h4_from_u2(col[(o + 19) * SQ]), b1 = h4_from_u2(col[(o + 20) * SQ]);
        H4 b2 = h4_from_u2(col[(o + 21) * SQ]);
        C[(o + 0) * SQ + q] = u2_from_h4(h4min(h4min(a0, a1),   h4min(a2, core)));
        C[(o + 1) * SQ + q] = u2_from_h4(h4min(h4min(a1, a2),   h4min(core, b0)));
        C[(o + 2) * SQ + q] = u2_from_h4(h4min(h4min(a2, core), h4min(b0, b1)));
        C[(o + 3) * SQ + q] = u2_from_h4(h4min(h4min(core, b0), h4min(b1, b2)));
    }
    __syncthreads();

    // x-min: SIMD-paired windows via PRMT slices (see R10 comments).
#pragma unroll
    for (int k = 0; k < 4; ++k) {
        const int i = tid + NT * k;          // 0..1279 exactly
        const int row = i / SQ, qq = i % SQ;
        unsigned h[14];
#pragma unroll
        for (int dq = -3; dq <= 3; ++dq) {
            const uint2 c = C[row * SQ + clampi(qq + dq, 0, SQ - 1)];
            h[2 * (dq + 3)]     = c.x;
            h[2 * (dq + 3) + 1] = c.y;
        }
        unsigned s[21];
#pragma unroll
        for (int j = 0; j < 21; ++j) {
            const int d = j - 9;
            if ((d & 1) == 0) {
                s[j] = h[(d + 12) >> 1];
            } else {
                s[j] = __byte_perm(h[(d + 11) >> 1], h[(d + 13) >> 1], 0x5432);
            }
        }
        unsigned c0 = umin2(s[2],  s[3]),  c1 = umin2(s[4],  s[5]);
        unsigned c2 = umin2(s[6],  s[7]),  c3 = umin2(s[8],  s[9]);
        unsigned c4 = umin2(s[10], s[11]), c5 = umin2(s[12], s[13]);
        unsigned c6 = umin2(s[14], s[15]), c7 = umin2(s[16], s[17]);
        unsigned d0 = umin2(c0, c1), d1 = umin2(c2, c3);
        unsigned d2 = umin2(c4, c5), d3 = umin2(c6, c7);
        unsigned core = umin2(umin2(umin2(d0, d1), umin2(d2, d3)), s[18]);
        uint2 r;
        r.x = umin2(umin2(s[0],  s[1]),  core);
        r.y = umin2(umin2(s[19], s[20]), core);
        outh[base4 + (long long)(y0 + row) * SQ + qq] = r;
    }
}

// ---------------------------------------------------------------------------
// Pass B: 19-min over z (fp16 tree) fused with the weighted-dice reduction.
// R10 structure (no register prefetch — occupancy rules here); the smem fill
// now moves uint4 (2 quads per LDG.128/STS.128).
// ---------------------------------------------------------------------------
__global__ void __launch_bounds__(NT) minz_reduce_kernel(const uint4* __restrict__ exy4w,
                                                         const float4* __restrict__ pred4,
                                                         const float4* __restrict__ targ4,
                                                         float* __restrict__ out) {
    __shared__ uint4 s4[50 * SQ2];           // 16000 B (50 rows * 20 uint4)
    __shared__ float wsum[NT / 32][3];

    const int tid = threadIdx.x;
    const int q   = tid % SQ;
    const int g   = tid / SQ;                // 0..7
    const int o   = 4 * g;
    const int z0  = blockIdx.x * TZ;
    const int y   = blockIdx.y;
    const int b   = blockIdx.z;
    const long long bbase4 = (long long)b * S * S * SQ;    // quad units
    const long long bbaseW = (long long)b * S * S * SQ2;   // uint4 units

    // Fill 50 z-rows, uint4-wide (1000 uint4 total, 3.125 per thread).
    for (int i = tid; i < 50 * SQ2; i += NT) {
        const int r = i / SQ2, j = i % SQ2;
        const int z = clampi(z0 - R + r, 0, S - 1);
        s4[i] = exy4w[bbaseW + (long long)z * S * SQ2 + y * SQ2 + j];
    }
    __syncthreads();

    const uint2* col = reinterpret_cast<const uint2*>(s4) + q;
    H4 p0 = h4min(h4_from_u2(col[(o + 3) * SQ]),  h4_from_u2(col[(o + 4) * SQ]));
    H4 p1 = h4min(h4_from_u2(col[(o + 5) * SQ]),  h4_from_u2(col[(o + 6) * SQ]));
    H4 p2 = h4min(h4_from_u2(col[(o + 7) * SQ]),  h4_from_u2(col[(o + 8) * SQ]));
    H4 p3 = h4min(h4_from_u2(col[(o + 9) * SQ]),  h4_from_u2(col[(o + 10) * SQ]));
    H4 p4 = h4min(h4_from_u2(col[(o + 11) * SQ]), h4_from_u2(col[(o + 12) * SQ]));
    H4 p5 = h4min(h4_from_u2(col[(o + 13) * SQ]), h4_from_u2(col[(o + 14) * SQ]));
    H4 p6 = h4min(h4_from_u2(col[(o + 15) * SQ]), h4_from_u2(col[(o + 16) * SQ]));
    H4 p7 = h4min(h4_from_u2(col[(o + 17) * SQ]), h4_from_u2(col[(o + 18) * SQ]));
    H4 core = h4min(h4min(h4min(p0, p1), h4min(p2, p3)),
                    h4min(h4min(p4, p5), h4min(p6, p7)));
    H4 a0 = h4_from_u2(col[(o + 0) * SQ]),  a1 = h4_from_u2(col[(o + 1) * SQ]);
    H4 a2 = h4_from_u2(col[(o + 2) * SQ]);
    H4 b0 = h4_from_u2(col[(o + 19) * SQ]), b1 = h4_from_u2(col[(o + 20) * SQ]);
    H4 b2 = h4_from_u2(col[(o + 21) * SQ]);
    H4 e[4];
    e[0] = h4min(h4min(a0, a1),   h4min(a2, core));
    e[1] = h4min(h4min(a1, a2),   h4min(core, b0));
    e[2] = h4min(h4min(a2, core), h4min(b0, b1));
    e[3] = h4min(h4min(core, b0), h4min(b1, b2));

    float aI = 0.f, aP = 0.f, aT = 0.f;
#pragma unroll
    for (int j = 0; j < 4; ++j) {
        const long long idx4 = bbase4 + (long long)(z0 + o + j) * S * SQ + y * SQ + q;
        const float4 p = pred4[idx4];
        const float4 t = targ4[idx4];
        const float2 elo = __half22float2(e[j].a);
        const float2 ehi = __half22float2(e[j].b);
        float w, wp;
        w = fmaf(t.x - elo.x, 5.0f, 1.0f); wp = w * p.x;
        aI = fmaf(wp, t.x, aI); aP += wp; aT = fmaf(w, t.x, aT);
        w = fmaf(t.y - elo.y, 5.0f, 1.0f); wp = w * p.y;
        aI = fmaf(wp, t.y, aI); aP += wp; aT = fmaf(w, t.y, aT);
        w = fmaf(t.z - ehi.x, 5.0f, 1.0f); wp = w * p.z;
        aI = fmaf(wp, t.z, aI); aP += wp; aT = fmaf(w, t.z, aT);
        w = fmaf(t.w - ehi.y, 5.0f, 1.0f); wp = w * p.w;
        aI = fmaf(wp, t.w, aI); aP += wp; aT = fmaf(w, t.w, aT);
    }

#pragma unroll
    for (int off = 16; off > 0; off >>= 1) {
        aI += __shfl_down_sync(0xFFFFFFFFu, aI, off);
        aP += __shfl_down_sync(0xFFFFFFFFu, aP, off);
        aT += __shfl_down_sync(0xFFFFFFFFu, aT, off);
    }
    const int wid = tid >> 5, lane = tid & 31;
    if (lane == 0) { wsum[wid][0] = aI; wsum[wid][1] = aP; wsum[wid][2] = aT; }
    __syncthreads();

    if (tid == 0) {
        double I = 0.0, P = 0.0, T = 0.0;
#pragma unroll
        for (int w = 0; w < NT / 32; ++w) {
            I += (double)wsum[w][0];
            P += (double)wsum[w][1];
            T += (double)wsum[w][2];
        }
        atomicAdd(&g_acc[0], I);
        atomicAdd(&g_acc[1], P);
        atomicAdd(&g_acc[2], T);
        __threadfence();
        const unsigned int n = atomicAdd(&g_done, 1u);
        if (n == NBLOCKS_B - 1) {
            g_done = 0;   // reset for next graph replay (only this block alive)
            const double fI = atomicAdd(&g_acc[0], 0.0);
            const double fP = atomicAdd(&g_acc[1], 0.0);
            const double fT = atomicAdd(&g_acc[2], 0.0);
            const double dice = (2.0 * fI + 1e-5) / (fP + fT + 1e-5);
            out[0] = (float)(1.0 - dice);
        }
    }
}

// ---------------------------------------------------------------------------
extern "C" void kernel_launch(void* const* d_in, const int* in_sizes, int n_in,
                              void* d_out, int out_size) {
    const float4* pred = (const float4*)d_in[0];
    const float4* targ = (const float4*)d_in[1];
    float* out = (float*)d_out;
    (void)in_sizes; (void)n_in; (void)out_size;

    uint4* exy; cudaGetSymbolAddress((void**)&exy, g_exy);

    const int smemA = (50 + TY) * SQ * (int)sizeof(uint2);   // 26240 B
    cudaFuncSetAttribute(minxy_kernel, cudaFuncAttributeMaxDynamicSharedMemorySize, smemA);

    dim3 gridA(S / TY, S, 4);    // (5, 160, 4)
    minxy_kernel<<<gridA, NT, smemA>>>(targ, (uint2*)exy);

    dim3 gridB(S / TZ, S, 4);    // (5, 160, 4)
    minz_reduce_kernel<<<gridB, NT>>>(exy, pred, targ, out);
}

// round 15
// speedup vs baseline: 1.3096x; 1.1133x over previous
#include <cuda_runtime.h>
#include <cuda_fp16.h>
#include <math.h>

#define S   160
#define SQ  40          // S/4 quads per row (quad = 4 fp16 elems, uint2)
#define SQ2 20          // uint4 (2 quads) per row
#define R   9           // 9x 3-erosion == one 19-window (clamped)
#define TY  40          // y-tile (pass A): halo 58/40 = 1.45x
#define HA  (TY + 2 * R)   // 58
#define TZ  32
#define NT  320
#define NBLOCKS_B ((S / TZ) * S * 4)   // 3200
#define NQUADS (4 * S * S * SQ)        // total fp16-quad count

// Scratch: eroded-xy field as packed fp16, declared uint4 (16B alignment for
// pass B's LDG.128 fill; pass A writes via an 8B-aligned uint2 view).
// min is monotonic => fp16-rounding before the min cascade == one rounding
// of the true eroded field.
__device__ uint4        g_exy[NQUADS / 2];
__device__ double       g_acc[3];
__device__ unsigned int g_done;   // zero-init; last block resets it each replay

__device__ __forceinline__ int clampi(int v, int lo, int hi) {
    return v < lo ? lo : (v > hi ? hi : v);
}

// ---- fp16 helpers -------------------------------------------------------
__device__ __forceinline__ unsigned h2_to_u(__half2 h) {
    return ((unsigned)__half_as_ushort(__high2half(h)) << 16) |
            (unsigned)__half_as_ushort(__low2half(h));
}
__device__ __forceinline__ __half2 u_to_h2(unsigned u) {
    return __halves2half2(__ushort_as_half((unsigned short)(u & 0xFFFFu)),
                          __ushort_as_half((unsigned short)(u >> 16)));
}
__device__ __forceinline__ unsigned umin2(unsigned a, unsigned b) {
    return h2_to_u(__hmin2(u_to_h2(a), u_to_h2(b)));
}
struct H4 { __half2 a, b; };
__device__ __forceinline__ H4 h4min(H4 x, H4 y) {
    H4 r; r.a = __hmin2(x.a, y.a); r.b = __hmin2(x.b, y.b); return r;
}
__device__ __forceinline__ H4 h4_from_u2(uint2 u) {
    H4 r; r.a = u_to_h2(u.x); r.b = u_to_h2(u.y); return r;
}
__device__ __forceinline__ uint2 u2_from_h4(H4 h) {
    uint2 u; u.x = h2_to_u(h.a); u.y = h2_to_u(h.b); return u;
}

// ---------------------------------------------------------------------------
// Pass A: fused 19-min over y then x, fp16. TY=40 (halo 1.45x).
// Block = (ytile, z, b), 320 threads. smem: A[58][40] + C[40][40] uint2.
// ---------------------------------------------------------------------------
__global__ void __launch_bounds__(NT) minxy_kernel(const float4* __restrict__ in4,
                                                   uint2* __restrict__ outh) {
    extern __shared__ uint2 smu[];
    uint2* A = smu;                  // HA*40
    uint2* C = smu + HA * SQ;        // TY*40

    const int tid = threadIdx.x;
    const int q   = tid % SQ;
    const int g   = tid / SQ;        // 0..7
    const int y0  = blockIdx.x * TY;
    const int z   = blockIdx.y;
    const int b   = blockIdx.z;
    const long long base4 = (long long)(b * S + z) * S * SQ;

    if (blockIdx.x == 0 && blockIdx.y == 0 && blockIdx.z == 0 && tid < 3)
        g_acc[tid] = 0.0;

    // Load HA y-rows (clamped halo), convert fp32->fp16 at load.
    for (int i = tid; i < HA * SQ; i += NT) {
        const int r = i / SQ, qq = i % SQ;
        const int y = clampi(y0 - R + r, 0, S - 1);
        const float4 f = in4[base4 + y * SQ + qq];
        uint2 u;
        u.x = h2_to_u(__floats2half2_rn(f.x, f.y));
        u.y = h2_to_u(__floats2half2_rn(f.z, f.w));
        A[i] = u;
    }
    __syncthreads();

    // y-min: 10 groups of 4 outputs; 8 thread-groups (g=0,1 take 2 groups).
    for (int gg = g; gg < TY / 4; gg += NT / SQ) {
        const int o = 4 * gg;
        const uint2* col = A + q;
        H4 p0 = h4min(h4_from_u2(col[(o + 3) * SQ]),  h4_from_u2(col[(o + 4) * SQ]));
        H4 p1 = h4min(h4_from_u2(col[(o + 5) * SQ]),  h4_from_u2(col[(o + 6) * SQ]));
        H4 p2 = h4min(h4_from_u2(col[(o + 7) * SQ]),  h4_from_u2(col[(o + 8) * SQ]));
        H4 p3 = h4min(h4_from_u2(col[(o + 9) * SQ]),  h4_from_u2(col[(o + 10) * SQ]));
        H4 p4 = h4min(h4_from_u2(col[(o + 11) * SQ]), h4_from_u2(col[(o + 12) * SQ]));
        H4 p5 = h4min(h4_from_u2(col[(o + 13) * SQ]), h4_from_u2(col[(o + 14) * SQ]));
        H4 p6 = h4min(h4_from_u2(col[(o + 15) * SQ]), h4_from_u2(col[(o + 16) * SQ]));
        H4 p7 = h4min(h4_from_u2(col[(o + 17) * SQ]), h4_from_u2(col[(o + 18) * SQ]));
        H4 core = h4min(h4min(h4min(p0, p1), h4min(p2, p3)),
                        h4min(h4min(p4, p5), h4min(p6, p7)));
        H4 a0 = h4_from_u2(col[(o + 0) * SQ]),  a1 = h4_from_u2(col[(o + 1) * SQ]);
        H4 a2 = h4_from_u2(col[(o + 2) * SQ]);
        H4 b0 = h4_from_u2(col[(o + 19) * SQ]), b1 = h4_from_u2(col[(o + 20) * SQ]);
        H4 b2 = h4_from_u2(col[(o + 21) * SQ]);
        C[(o + 0) * SQ + q] = u2_from_h4(h4min(h4min(a0, a1),   h4min(a2, core)));
        C[(o + 1) * SQ + q] = u2_from_h4(h4min(h4min(a1, a2),   h4min(core, b0)));
        C[(o + 2) * SQ + q] = u2_from_h4(h4min(h4min(a2, core), h4min(b0, b1)));
        C[(o + 3) * SQ + q] = u2_from_h4(h4min(h4min(core, b0), h4min(b1, b2)));
    }
    __syncthreads();

    // x-min: SIMD-paired windows via PRMT slices. 1600 quads / 320 = 5 iters.
#pragma unroll
    for (int k = 0; k < (TY * SQ) / NT; ++k) {
        const int i = tid + NT * k;
        const int row = i / SQ, qq = i % SQ;
        unsigned h[14];
#pragma unroll
        for (int dq = -3; dq <= 3; ++dq) {
            const uint2 c = C[row * SQ + clampi(qq + dq, 0, SQ - 1)];
            h[2 * (dq + 3)]     = c.x;
            h[2 * (dq + 3) + 1] = c.y;
        }
        unsigned s[21];
#pragma unroll
        for (int j = 0; j < 21; ++j) {
            const int d = j - 9;
            if ((d & 1) == 0) {
                s[j] = h[(d + 12) >> 1];
            } else {
                s[j] = __byte_perm(h[(d + 11) >> 1], h[(d + 13) >> 1], 0x5432);
            }
        }
        unsigned c0 = umin2(s[2],  s[3]),  c1 = umin2(s[4],  s[5]);
        unsigned c2 = umin2(s[6],  s[7]),  c3 = umin2(s[8],  s[9]);
        unsigned c4 = umin2(s[10], s[11]), c5 = umin2(s[12], s[13]);
        unsigned c6 = umin2(s[14], s[15]), c7 = umin2(s[16], s[17]);
        unsigned d0 = umin2(c0, c1), d1 = umin2(c2, c3);
        unsigned d2 = umin2(c4, c5), d3 = umin2(c6, c7);
        unsigned core = umin2(umin2(umin2(d0, d1), umin2(d2, d3)), s[18]);
        uint2 r;
        r.x = umin2(umin2(s[0],  s[1]),  core);
        r.y = umin2(umin2(s[19], s[20]), core);
        outh[base4 + (long long)(y0 + row) * SQ + qq] = r;
    }
}

// ---------------------------------------------------------------------------
// Pass B: 19-min over z (fp16 tree) + weighted-dice reduction. R13 shape;
// pred/targ loads use __ldcs (read-once, evict-first) so the exy field stays
// L2-resident and its halo reads hit L2 instead of DRAM.
// ---------------------------------------------------------------------------
__global__ void __launch_bounds__(NT) minz_reduce_kernel(const uint4* __restrict__ exy4w,
                                                         const float4* __restrict__ pred4,
                                                         const float4* __restrict__ targ4,
                                                         float* __restrict__ out) {
    __shared__ uint4 s4[50 * SQ2];           // 16000 B
    __shared__ float wsum[NT / 32][3];

    const int tid = threadIdx.x;
    const int q   = tid % SQ;
    const int g   = tid / SQ;                // 0..7
    const int o   = 4 * g;
    const int z0  = blockIdx.x * TZ;
    const int y   = blockIdx.y;
    const int b   = blockIdx.z;
    const long long bbase4 = (long long)b * S * S * SQ;    // quad units
    const long long bbaseW = (long long)b * S * S * SQ2;   // uint4 units

    for (int i = tid; i < 50 * SQ2; i += NT) {
        const int r = i / SQ2, j = i % SQ2;
        const int z = clampi(z0 - R + r, 0, S - 1);
        s4[i] = exy4w[bbaseW + (long long)z * S * SQ2 + y * SQ2 + j];
    }
    __syncthreads();

    const uint2* col = reinterpret_cast<const uint2*>(s4) + q;
    H4 p0 = h4min(h4_from_u2(col[(o + 3) * SQ]),  h4_from_u2(col[(o + 4) * SQ]));
    H4 p1 = h4min(h4_from_u2(col[(o + 5) * SQ]),  h4_from_u2(col[(o + 6) * SQ]));
    H4 p2 = h4min(h4_from_u2(col[(o + 7) * SQ]),  h4_from_u2(col[(o + 8) * SQ]));
    H4 p3 = h4min(h4_from_u2(col[(o + 9) * SQ]),  h4_from_u2(col[(o + 10) * SQ]));
    H4 p4 = h4min(h4_from_u2(col[(o + 11) * SQ]), h4_from_u2(col[(o + 12) * SQ]));
    H4 p5 = h4min(h4_from_u2(col[(o + 13) * SQ]), h4_from_u2(col[(o + 14) * SQ]));
    H4 p6 = h4min(h4_from_u2(col[(o + 15) * SQ]), h4_from_u2(col[(o + 16) * SQ]));
    H4 p7 = h4min(h4_from_u2(col[(o + 17) * SQ]), h4_from_u2(col[(o + 18) * SQ]));
    H4 core = h4min(h4min(h4min(p0, p1), h4min(p2, p3)),
                    h4min(h4min(p4, p5), h4min(p6, p7)));
    H4 a0 = h4_from_u2(col[(o + 0) * SQ]),  a1 = h4_from_u2(col[(o + 1) * SQ]);
    H4 a2 = h4_from_u2(col[(o + 2) * SQ]);
    H4 b0 = h4_from_u2(col[(o + 19) * SQ]), b1 = h4_from_u2(col[(o + 20) * SQ]);
    H4 b2 = h4_from_u2(col[(o + 21) * SQ]);
    H4 e[4];
    e[0] = h4min(h4min(a0, a1),   h4min(a2, core));
    e[1] = h4min(h4min(a1, a2),   h4min(core, b0));
    e[2] = h4min(h4min(a2, core), h4min(b0, b1));
    e[3] = h4min(h4min(core, b0), h4min(b1, b2));

    float aI = 0.f, aP = 0.f, aT = 0.f;
#pragma unroll
    for (int j = 0; j < 4; ++j) {
        const long long idx4 = bbase4 + (long long)(z0 + o + j) * S * SQ + y * SQ + q;
        const float4 p = __ldcs(pred4 + idx4);
        const float4 t = __ldcs(targ4 + idx4);
        const float2 elo = __half22float2(e[j].a);
        const float2 ehi = __half22float2(e[j].b);
        float w, wp;
        w = fmaf(t.x - elo.x, 5.0f, 1.0f); wp = w * p.x;
        aI = fmaf(wp, t.x, aI); aP += wp; aT = fmaf(w, t.x, aT);
        w = fmaf(t.y - elo.y, 5.0f, 1.0f); wp = w * p.y;
        aI = fmaf(wp, t.y, aI); aP += wp; aT = fmaf(w, t.y, aT);
        w = fmaf(t.z - ehi.x, 5.0f, 1.0f); wp = w * p.z;
        aI = fmaf(wp, t.z, aI); aP += wp; aT = fmaf(w, t.z, aT);
        w = fmaf(t.w - ehi.y, 5.0f, 1.0f); wp = w * p.w;
        aI = fmaf(wp, t.w, aI); aP += wp; aT = fmaf(w, t.w, aT);
    }

#pragma unroll
    for (int off = 16; off > 0; off >>= 1) {
        aI += __shfl_down_sync(0xFFFFFFFFu, aI, off);
        aP += __shfl_down_sync(0xFFFFFFFFu, aP, off);
        aT += __shfl_down_sync(0xFFFFFFFFu, aT, off);
    }
    const int wid = tid >> 5, lane = tid & 31;
    if (lane == 0) { wsum[wid][0] = aI; wsum[wid][1] = aP; wsum[wid][2] = aT; }
    __syncthreads();

    if (tid == 0) {
        double I = 0.0, P = 0.0, T = 0.0;
#pragma unroll
        for (int w = 0; w < NT / 32; ++w) {
            I += (double)wsum[w][0];
            P += (double)wsum[w][1];
            T += (double)wsum[w][2];
        }
        atomicAdd(&g_acc[0], I);
        atomicAdd(&g_acc[1], P);
        atomicAdd(&g_acc[2], T);
        __threadfence();
        const unsigned int n = atomicAdd(&g_done, 1u);
        if (n == NBLOCKS_B - 1) {
            g_done = 0;   // reset for next graph replay (only this block alive)
            const double fI = atomicAdd(&g_acc[0], 0.0);
            const double fP = atomicAdd(&g_acc[1], 0.0);
            const double fT = atomicAdd(&g_acc[2], 0.0);
            const double dice = (2.0 * fI + 1e-5) / (fP + fT + 1e-5);
            out[0] = (float)(1.0 - dice);
        }
    }
}

// ---------------------------------------------------------------------------
extern "C" void kernel_launch(void* const* d_in, const int* in_sizes, int n_in,
                              void* d_out, int out_size) {
    const float4* pred = (const float4*)d_in[0];
    const float4* targ = (const float4*)d_in[1];
    float* out = (float*)d_out;
    (void)in_sizes; (void)n_in; (void)out_size;

    uint4* exy; cudaGetSymbolAddress((void**)&exy, g_exy);

    const int smemA = (HA + TY) * SQ * (int)sizeof(uint2);   // 31360 B
    cudaFuncSetAttribute(minxy_kernel, cudaFuncAttributeMaxDynamicSharedMemorySize, smemA);

    dim3 gridA(S / TY, S, 4);    // (4, 160, 4)
    minxy_kernel<<<gridA, NT, smemA>>>(targ, (uint2*)exy);

    dim3 gridB(S / TZ, S, 4);    // (5, 160, 4)
    minz_reduce_kernel<<<gridB, NT>>>(exy, pred, targ, out);
}